// round 9
// baseline (speedup 1.0000x reference)
#include <cuda_runtime.h>
#include <math.h>

#define BB 64
#define PP 256
#define NN 4096
#define SPLITK 64
#define KC (NN / SPLITK)   // 64
#define KCH 32
#define SPLITP 4
#define PCH (PP / SPLITP)  // 64

typedef unsigned long long ull;

// Interleaved (cos, sin) tables
__device__ __align__(16) float2 g_csphi[BB * NN];
__device__ __align__(16) float2 g_csxi[PP * NN];
__device__ float g_mpart[SPLITK * BB * PP];
__device__ float g_w[BB * PP];
__device__ __align__(16) ull g_cpart[SPLITP][BB * NN];  // packed (Wc, Ws) partials

// Packed fp32x2 FMA (Blackwell FFMA2)
__device__ __forceinline__ ull ffma2(ull a, ull b, ull c) {
    ull d;
    asm("fma.rn.f32x2 %0, %1, %2, %3;" : "=l"(d) : "l"(a), "l"(b), "l"(c));
    return d;
}
__device__ __forceinline__ ull pack2(float x, float y) {
    ull r; asm("mov.b64 %0, {%1, %2};" : "=l"(r) : "f"(x), "f"(y)); return r;
}
__device__ __forceinline__ float2 unpack2(ull v) {
    float2 f; asm("mov.b64 {%0, %1}, %2;" : "=f"(f.x), "=f"(f.y) : "l"(v)); return f;
}

// ---------------------------------------------------------------------------
// Kernel 1: trig tables, interleaved (cos, sin)
// ---------------------------------------------------------------------------
__global__ __launch_bounds__(256) void trig_kernel(const float* __restrict__ phi,
                                                   const float* __restrict__ xi) {
    int i = blockIdx.x * 256 + threadIdx.x;
    if (i < BB * NN) {
        float s, c;
        sincosf(phi[i], &s, &c);
        g_csphi[i] = make_float2(c, s);
    } else if (i < (BB + PP) * NN) {
        int j = i - BB * NN;
        float s, c;
        sincosf(xi[j], &s, &c);
        g_csxi[j] = make_float2(c, s);
    }
}

// ---------------------------------------------------------------------------
// Kernel 2: m[b,p] = sum_k dot2(csphi[b,k], csxi[p,k]) via fma2.
// GEMM M=64(b), N=256(p), K=4096, split-K=64. grid=(4,64)=256 blocks.
// ---------------------------------------------------------------------------
__global__ __launch_bounds__(256) void mgemm_kernel() {
    __shared__ __align__(16) float4 Asm[64][17];
    __shared__ __align__(16) float2 Bsm[32][66];

    int p0 = blockIdx.x * 64;
    int k0 = blockIdx.y * KC;
    int tid = threadIdx.x;
    int tx = tid & 15;
    int ty = tid >> 4;

    ull acc[4][4] = {};

    const float4* A4 = (const float4*)g_csphi;
    const float4* B4 = (const float4*)g_csxi;

    for (int kk = 0; kk < KC; kk += KCH) {
        int kc4 = (k0 + kk) >> 1;
#pragma unroll
        for (int i = tid; i < 64 * 16; i += 256) {
            int r = i >> 4, c = i & 15;
            Asm[r][c] = A4[r * (NN / 2) + kc4 + c];
            float4 v = B4[(p0 + r) * (NN / 2) + kc4 + c];
            Bsm[2 * c][r] = make_float2(v.x, v.y);
            Bsm[2 * c + 1][r] = make_float2(v.z, v.w);
        }
        __syncthreads();
#pragma unroll
        for (int kp = 0; kp < 16; kp++) {
            ulonglong2 av[4];
#pragma unroll
            for (int i = 0; i < 4; i++)
                av[i] = *(const ulonglong2*)&Asm[ty * 4 + i][kp];
            ulonglong2 b0a = *(const ulonglong2*)&Bsm[2 * kp][2 * tx];
            ulonglong2 b0b = *(const ulonglong2*)&Bsm[2 * kp][2 * tx + 32];
            ulonglong2 b1a = *(const ulonglong2*)&Bsm[2 * kp + 1][2 * tx];
            ulonglong2 b1b = *(const ulonglong2*)&Bsm[2 * kp + 1][2 * tx + 32];
#pragma unroll
            for (int i = 0; i < 4; i++) {
                acc[i][0] = ffma2(av[i].x, b0a.x, acc[i][0]);
                acc[i][1] = ffma2(av[i].x, b0a.y, acc[i][1]);
                acc[i][2] = ffma2(av[i].x, b0b.x, acc[i][2]);
                acc[i][3] = ffma2(av[i].x, b0b.y, acc[i][3]);
                acc[i][0] = ffma2(av[i].y, b1a.x, acc[i][0]);
                acc[i][1] = ffma2(av[i].y, b1a.y, acc[i][1]);
                acc[i][2] = ffma2(av[i].y, b1b.x, acc[i][2]);
                acc[i][3] = ffma2(av[i].y, b1b.y, acc[i][3]);
            }
        }
        __syncthreads();
    }

    float* outp = g_mpart + blockIdx.y * (BB * PP);
    int poff[4] = {2 * tx, 2 * tx + 1, 2 * tx + 32, 2 * tx + 33};
#pragma unroll
    for (int i = 0; i < 4; i++)
#pragma unroll
        for (int j = 0; j < 4; j++) {
            float2 f = unpack2(acc[i][j]);
            outp[(ty * 4 + i) * PP + p0 + poff[j]] = f.x + f.y;
        }
}

// ---------------------------------------------------------------------------
// Kernel 3: reduce split-K partials, softmax over p (per b).
// ---------------------------------------------------------------------------
__global__ __launch_bounds__(256) void softmax_kernel() {
    __shared__ float red[256];
    int b = blockIdx.x;
    int p = threadIdx.x;

    float s = 0.f;
#pragma unroll
    for (int sp = 0; sp < SPLITK; sp++)
        s += g_mpart[sp * BB * PP + b * PP + p];

    float val = s * (1.0f / (float)NN);

    red[p] = val;
    __syncthreads();
    for (int off = 128; off > 0; off >>= 1) {
        if (p < off) red[p] = fmaxf(red[p], red[p + off]);
        __syncthreads();
    }
    float mx = red[0];
    __syncthreads();

    float e = expf(val - mx);
    red[p] = e;
    __syncthreads();
    for (int off = 128; off > 0; off >>= 1) {
        if (p < off) red[p] += red[p + off];
        __syncthreads();
    }
    g_w[b * PP + p] = e / red[0];
}

// ---------------------------------------------------------------------------
// Kernel 4: coupling GEMM (split-P partials), fma2.
//   (Wc,Ws)[sp][b,n] = sum_{p in slice} w[b,p] * (cxi,sxi)[p,n]
// Tile 32b x 64n x 64p. 256 thr (16 n-thr x 16 b-thr), micro 2b x 4n.
// grid = (NN/64, BB/32, SPLITP) = (64, 2, 4) = 512 blocks.
// ---------------------------------------------------------------------------
__global__ __launch_bounds__(256) void coupling_kernel() {
    __shared__ __align__(16) float2 Csm[32][66];  // [p-chunk][n]
    __shared__ float Wsm[32][33];                 // [b][p-chunk]

    int n0 = blockIdx.x * 64;
    int b0 = blockIdx.y * 32;
    int ps0 = blockIdx.z * PCH;
    int tid = threadIdx.x;
    int tx = tid & 15;   // n-thread: n = n0 + 4*tx .. +3
    int ty = tid >> 4;   // b-thread: b = b0 + 2*ty, 2*ty+1

    ull acc[2][4] = {};
    const float4* X4 = (const float4*)g_csxi;

    for (int pk = 0; pk < PCH; pk += 32) {
#pragma unroll
        for (int i = tid; i < 32 * 32; i += 256) {
            int r = i >> 5, c = i & 31;
            float4 v = X4[(ps0 + pk + r) * (NN / 2) + (n0 >> 1) + c];
            Csm[r][2 * c] = make_float2(v.x, v.y);
            Csm[r][2 * c + 1] = make_float2(v.z, v.w);
        }
#pragma unroll
        for (int i = tid; i < 32 * 32; i += 256) {
            int r = i >> 5, c = i & 31;
            Wsm[r][c] = g_w[(b0 + r) * PP + ps0 + pk + c];
        }
        __syncthreads();
#pragma unroll
        for (int p = 0; p < 32; p++) {
            ulonglong2 c01 = *(const ulonglong2*)&Csm[p][4 * tx];
            ulonglong2 c23 = *(const ulonglong2*)&Csm[p][4 * tx + 2];
            float w0 = Wsm[2 * ty][p];
            float w1 = Wsm[2 * ty + 1][p];
            ull w02 = pack2(w0, w0);
            ull w12 = pack2(w1, w1);
            acc[0][0] = ffma2(w02, c01.x, acc[0][0]);
            acc[0][1] = ffma2(w02, c01.y, acc[0][1]);
            acc[0][2] = ffma2(w02, c23.x, acc[0][2]);
            acc[0][3] = ffma2(w02, c23.y, acc[0][3]);
            acc[1][0] = ffma2(w12, c01.x, acc[1][0]);
            acc[1][1] = ffma2(w12, c01.y, acc[1][1]);
            acc[1][2] = ffma2(w12, c23.x, acc[1][2]);
            acc[1][3] = ffma2(w12, c23.y, acc[1][3]);
        }
        __syncthreads();
    }

    ull* outp = g_cpart[blockIdx.z];
#pragma unroll
    for (int ib = 0; ib < 2; ib++) {
        int base = (b0 + 2 * ty + ib) * NN + n0 + 4 * tx;
        *(ulonglong2*)&outp[base] = make_ulonglong2(acc[ib][0], acc[ib][1]);
        *(ulonglong2*)&outp[base + 2] = make_ulonglong2(acc[ib][2], acc[ib][3]);
    }
}

// ---------------------------------------------------------------------------
// Kernel 5: combine split-P partials + anchor epilogue.
//   out[b,n] = sphi*Wc - cphi*Ws + A*(sin(wt)*cphi - cos(wt)*sphi)
// ---------------------------------------------------------------------------
__global__ __launch_bounds__(256) void finish_kernel(const float* __restrict__ t,
                                                     float* __restrict__ out) {
    int i = blockIdx.x * 256 + threadIdx.x;  // pair index over BB*NN/2

    float2 a0 = make_float2(0.f, 0.f);
    float2 a1 = make_float2(0.f, 0.f);
#pragma unroll
    for (int sp = 0; sp < SPLITP; sp++) {
        ulonglong2 v = *(const ulonglong2*)&g_cpart[sp][2 * i];
        float2 f0 = unpack2(v.x), f1 = unpack2(v.y);
        a0.x += f0.x; a0.y += f0.y;
        a1.x += f1.x; a1.y += f1.y;
    }

    float tv = t[0];
    double sd, cd;
    sincos((double)(1256.6370614359172f * tv), &sd, &cd);
    float st = (float)sd, ct = (float)cd;

    const float4* P4 = (const float4*)g_csphi;
    float4 cs = P4[i];  // (cphi0, sphi0, cphi1, sphi1)

    float2 o;
    o.x = cs.y * a0.x - cs.x * a0.y + 0.08f * (st * cs.x - ct * cs.y);
    o.y = cs.w * a1.x - cs.z * a1.y + 0.08f * (st * cs.z - ct * cs.w);
    *(float2*)&out[2 * i] = o;
}

// ---------------------------------------------------------------------------
extern "C" void kernel_launch(void* const* d_in, const int* in_sizes, int n_in,
                              void* d_out, int out_size) {
    const float* t = nullptr;
    const float* phi = nullptr;
    const float* xi = nullptr;
    for (int i = 0; i < n_in; i++) {
        if (in_sizes[i] == 1) t = (const float*)d_in[i];
        else if (in_sizes[i] == BB * NN) phi = (const float*)d_in[i];
        else if (in_sizes[i] == PP * NN) xi = (const float*)d_in[i];
    }
    float* out = (float*)d_out;

    trig_kernel<<<((BB + PP) * NN + 255) / 256, 256>>>(phi, xi);
    mgemm_kernel<<<dim3(PP / 64, SPLITK), 256>>>();
    softmax_kernel<<<BB, 256>>>();
    coupling_kernel<<<dim3(NN / 64, BB / 32, SPLITP), 256>>>();
    finish_kernel<<<(BB * NN / 2) / 256, 256>>>(t, out);
}

// round 10
// speedup vs baseline: 1.0309x; 1.0309x over previous
#include <cuda_runtime.h>
#include <math.h>

#define BB 64
#define PP 256
#define NN 4096
#define SPLITK 128
#define KC (NN / SPLITK)   // 32 (one chunk per block)
#define SPLITP 8
#define PCH (PP / SPLITP)  // 32 (one chunk per block)

typedef unsigned long long ull;

// Interleaved (cos, sin) tables
__device__ __align__(16) float2 g_csphi[BB * NN];
__device__ __align__(16) float2 g_csxi[PP * NN];
__device__ float g_mpart[SPLITK * BB * PP];
__device__ float g_w[BB * PP];
__device__ __align__(16) ull g_cpart[SPLITP][BB * NN];  // packed (Wc, Ws) partials

// Packed fp32x2 FMA (Blackwell FFMA2)
__device__ __forceinline__ ull ffma2(ull a, ull b, ull c) {
    ull d;
    asm("fma.rn.f32x2 %0, %1, %2, %3;" : "=l"(d) : "l"(a), "l"(b), "l"(c));
    return d;
}
__device__ __forceinline__ ull pack2(float x, float y) {
    ull r; asm("mov.b64 %0, {%1, %2};" : "=l"(r) : "f"(x), "f"(y)); return r;
}
__device__ __forceinline__ float2 unpack2(ull v) {
    float2 f; asm("mov.b64 {%0, %1}, %2;" : "=f"(f.x), "=f"(f.y) : "l"(v)); return f;
}

// ---------------------------------------------------------------------------
// Kernel 1: trig tables, interleaved (cos, sin)
// ---------------------------------------------------------------------------
__global__ __launch_bounds__(256) void trig_kernel(const float* __restrict__ phi,
                                                   const float* __restrict__ xi) {
    int i = blockIdx.x * 256 + threadIdx.x;
    if (i < BB * NN) {
        float s, c;
        sincosf(phi[i], &s, &c);
        g_csphi[i] = make_float2(c, s);
    } else if (i < (BB + PP) * NN) {
        int j = i - BB * NN;
        float s, c;
        sincosf(xi[j], &s, &c);
        g_csxi[j] = make_float2(c, s);
    }
}

// ---------------------------------------------------------------------------
// Kernel 2: m[b,p] = sum_k dot2(csphi[b,k], csxi[p,k]) via fma2.
// GEMM M=64(b), N=256(p), K=4096, split-K=128 (32 k per block, single chunk).
// grid = (4, 128) = 512 blocks. Block 256 thr (16x16), tile 64b x 64p, micro 4x4.
// ---------------------------------------------------------------------------
__global__ __launch_bounds__(256) void mgemm_kernel() {
    __shared__ __align__(16) float4 Asm[64][17];   // [b][kpair]
    __shared__ __align__(16) float2 Bsm[32][66];   // [k][p] transposed

    int p0 = blockIdx.x * 64;
    int k0 = blockIdx.y * KC;
    int tid = threadIdx.x;
    int tx = tid & 15;
    int ty = tid >> 4;

    ull acc[4][4] = {};

    const float4* A4 = (const float4*)g_csphi;
    const float4* B4 = (const float4*)g_csxi;

    int kc4 = k0 >> 1;
#pragma unroll
    for (int i = tid; i < 64 * 16; i += 256) {
        int r = i >> 4, c = i & 15;
        Asm[r][c] = A4[r * (NN / 2) + kc4 + c];
        float4 v = B4[(p0 + r) * (NN / 2) + kc4 + c];
        Bsm[2 * c][r] = make_float2(v.x, v.y);
        Bsm[2 * c + 1][r] = make_float2(v.z, v.w);
    }
    __syncthreads();
#pragma unroll
    for (int kp = 0; kp < 16; kp++) {
        ulonglong2 av[4];
#pragma unroll
        for (int i = 0; i < 4; i++)
            av[i] = *(const ulonglong2*)&Asm[ty * 4 + i][kp];
        ulonglong2 b0a = *(const ulonglong2*)&Bsm[2 * kp][2 * tx];
        ulonglong2 b0b = *(const ulonglong2*)&Bsm[2 * kp][2 * tx + 32];
        ulonglong2 b1a = *(const ulonglong2*)&Bsm[2 * kp + 1][2 * tx];
        ulonglong2 b1b = *(const ulonglong2*)&Bsm[2 * kp + 1][2 * tx + 32];
#pragma unroll
        for (int i = 0; i < 4; i++) {
            acc[i][0] = ffma2(av[i].x, b0a.x, acc[i][0]);
            acc[i][1] = ffma2(av[i].x, b0a.y, acc[i][1]);
            acc[i][2] = ffma2(av[i].x, b0b.x, acc[i][2]);
            acc[i][3] = ffma2(av[i].x, b0b.y, acc[i][3]);
            acc[i][0] = ffma2(av[i].y, b1a.x, acc[i][0]);
            acc[i][1] = ffma2(av[i].y, b1a.y, acc[i][1]);
            acc[i][2] = ffma2(av[i].y, b1b.x, acc[i][2]);
            acc[i][3] = ffma2(av[i].y, b1b.y, acc[i][3]);
        }
    }

    float* outp = g_mpart + blockIdx.y * (BB * PP);
    int poff[4] = {2 * tx, 2 * tx + 1, 2 * tx + 32, 2 * tx + 33};
#pragma unroll
    for (int i = 0; i < 4; i++)
#pragma unroll
        for (int j = 0; j < 4; j++) {
            float2 f = unpack2(acc[i][j]);
            outp[(ty * 4 + i) * PP + p0 + poff[j]] = f.x + f.y;
        }
}

// ---------------------------------------------------------------------------
// Kernel 3: reduce split-K partials, softmax over p (per b).
// ---------------------------------------------------------------------------
__global__ __launch_bounds__(256) void softmax_kernel() {
    __shared__ float red[256];
    int b = blockIdx.x;
    int p = threadIdx.x;

    float s = 0.f;
#pragma unroll 8
    for (int sp = 0; sp < SPLITK; sp++)
        s += g_mpart[sp * BB * PP + b * PP + p];

    float val = s * (1.0f / (float)NN);

    red[p] = val;
    __syncthreads();
    for (int off = 128; off > 0; off >>= 1) {
        if (p < off) red[p] = fmaxf(red[p], red[p + off]);
        __syncthreads();
    }
    float mx = red[0];
    __syncthreads();

    float e = expf(val - mx);
    red[p] = e;
    __syncthreads();
    for (int off = 128; off > 0; off >>= 1) {
        if (p < off) red[p] += red[p + off];
        __syncthreads();
    }
    g_w[b * PP + p] = e / red[0];
}

// ---------------------------------------------------------------------------
// Kernel 4: coupling GEMM (split-P partials), fma2, micro 4b x 4n.
//   (Wc,Ws)[sp][b,n] = sum_{p in slice} w[b,p] * (cxi,sxi)[p,n]
// Tile: ALL 64 b x 64 n x 32 p per block (single chunk, one sync).
// 256 thr: tx 0..15 (n, 4 each), ty 0..15 (b, 4 each).
// grid = (NN/64, SPLITP) = (64, 8) = 512 blocks.
// Each C-tile LDS.128 feeds 4 b rows -> 3 smem bytes per FFMA2.
// ---------------------------------------------------------------------------
__global__ __launch_bounds__(256) void coupling_kernel() {
    __shared__ __align__(16) float2 Csm[PCH][66];  // [p][n] (c,s)
    __shared__ float Wsm[64][33];                  // [b][p]

    int n0 = blockIdx.x * 64;
    int ps0 = blockIdx.y * PCH;
    int tid = threadIdx.x;
    int tx = tid & 15;   // n-thread: n = n0 + 4*tx .. +3
    int ty = tid >> 4;   // b-thread: b = 4*ty .. +3

    const float4* X4 = (const float4*)g_csxi;

    // Stage C: 32 p x 32 float4 (= 64 n as (c,s) pairs)
#pragma unroll
    for (int i = tid; i < PCH * 32; i += 256) {
        int r = i >> 5, c = i & 31;
        float4 v = X4[(ps0 + r) * (NN / 2) + (n0 >> 1) + c];
        Csm[r][2 * c] = make_float2(v.x, v.y);
        Csm[r][2 * c + 1] = make_float2(v.z, v.w);
    }
    // Stage W: 64 b x 32 p
#pragma unroll
    for (int i = tid; i < 64 * PCH; i += 256) {
        int r = i >> 5, c = i & 31;
        Wsm[r][c] = g_w[r * PP + ps0 + c];
    }
    __syncthreads();

    ull acc[4][4] = {};
#pragma unroll
    for (int p = 0; p < PCH; p++) {
        ulonglong2 c01 = *(const ulonglong2*)&Csm[p][4 * tx];
        ulonglong2 c23 = *(const ulonglong2*)&Csm[p][4 * tx + 2];
        ull w2[4];
#pragma unroll
        for (int i = 0; i < 4; i++) {
            float w = Wsm[4 * ty + i][p];
            w2[i] = pack2(w, w);
        }
#pragma unroll
        for (int i = 0; i < 4; i++) {
            acc[i][0] = ffma2(w2[i], c01.x, acc[i][0]);
            acc[i][1] = ffma2(w2[i], c01.y, acc[i][1]);
            acc[i][2] = ffma2(w2[i], c23.x, acc[i][2]);
            acc[i][3] = ffma2(w2[i], c23.y, acc[i][3]);
        }
    }

    ull* outp = g_cpart[blockIdx.y];
#pragma unroll
    for (int i = 0; i < 4; i++) {
        int base = (4 * ty + i) * NN + n0 + 4 * tx;
        *(ulonglong2*)&outp[base] = make_ulonglong2(acc[i][0], acc[i][1]);
        *(ulonglong2*)&outp[base + 2] = make_ulonglong2(acc[i][2], acc[i][3]);
    }
}

// ---------------------------------------------------------------------------
// Kernel 5: combine split-P partials + anchor epilogue.
//   out[b,n] = sphi*Wc - cphi*Ws + A*(sin(wt)*cphi - cos(wt)*sphi)
// ---------------------------------------------------------------------------
__global__ __launch_bounds__(256) void finish_kernel(const float* __restrict__ t,
                                                     float* __restrict__ out) {
    int i = blockIdx.x * 256 + threadIdx.x;  // pair index over BB*NN/2

    float2 a0 = make_float2(0.f, 0.f);
    float2 a1 = make_float2(0.f, 0.f);
#pragma unroll
    for (int sp = 0; sp < SPLITP; sp++) {
        ulonglong2 v = *(const ulonglong2*)&g_cpart[sp][2 * i];
        float2 f0 = unpack2(v.x), f1 = unpack2(v.y);
        a0.x += f0.x; a0.y += f0.y;
        a1.x += f1.x; a1.y += f1.y;
    }

    float tv = t[0];
    double sd, cd;
    sincos((double)(1256.6370614359172f * tv), &sd, &cd);
    float st = (float)sd, ct = (float)cd;

    const float4* P4 = (const float4*)g_csphi;
    float4 cs = P4[i];  // (cphi0, sphi0, cphi1, sphi1)

    float2 o;
    o.x = cs.y * a0.x - cs.x * a0.y + 0.08f * (st * cs.x - ct * cs.y);
    o.y = cs.w * a1.x - cs.z * a1.y + 0.08f * (st * cs.z - ct * cs.w);
    *(float2*)&out[2 * i] = o;
}

// ---------------------------------------------------------------------------
extern "C" void kernel_launch(void* const* d_in, const int* in_sizes, int n_in,
                              void* d_out, int out_size) {
    const float* t = nullptr;
    const float* phi = nullptr;
    const float* xi = nullptr;
    for (int i = 0; i < n_in; i++) {
        if (in_sizes[i] == 1) t = (const float*)d_in[i];
        else if (in_sizes[i] == BB * NN) phi = (const float*)d_in[i];
        else if (in_sizes[i] == PP * NN) xi = (const float*)d_in[i];
    }
    float* out = (float*)d_out;

    trig_kernel<<<((BB + PP) * NN + 255) / 256, 256>>>(phi, xi);
    mgemm_kernel<<<dim3(PP / 64, SPLITK), 256>>>();
    softmax_kernel<<<BB, 256>>>();
    coupling_kernel<<<dim3(NN / 64, SPLITP), 256>>>();
    finish_kernel<<<(BB * NN / 2) / 256, 256>>>(t, out);
}

// round 11
// speedup vs baseline: 1.2387x; 1.2015x over previous
#include <cuda_runtime.h>
#include <math.h>

#define BB 64
#define PP 256
#define NN 4096
#define SPLITK 64
#define KC (NN / SPLITK)   // 64 (two 32-k chunks per block)
#define KCH 32
#define SPLITP 8
#define PCH (PP / SPLITP)  // 32 (one chunk per block)

typedef unsigned long long ull;

// Interleaved (cos, sin) tables
__device__ __align__(16) float2 g_csphi[BB * NN];
__device__ __align__(16) float2 g_csxi[PP * NN];
__device__ float g_mpart[SPLITK * BB * PP];
__device__ float g_w[BB * PP];
__device__ __align__(16) ull g_cpart[SPLITP][BB * NN];  // packed (Wc, Ws) partials

// Packed fp32x2 FMA (Blackwell FFMA2)
__device__ __forceinline__ ull ffma2(ull a, ull b, ull c) {
    ull d;
    asm("fma.rn.f32x2 %0, %1, %2, %3;" : "=l"(d) : "l"(a), "l"(b), "l"(c));
    return d;
}
__device__ __forceinline__ ull pack2(float x, float y) {
    ull r; asm("mov.b64 %0, {%1, %2};" : "=l"(r) : "f"(x), "f"(y)); return r;
}
__device__ __forceinline__ float2 unpack2(ull v) {
    float2 f; asm("mov.b64 {%0, %1}, %2;" : "=f"(f.x), "=f"(f.y) : "l"(v)); return f;
}

// ---------------------------------------------------------------------------
// Kernel 1: trig tables, interleaved (cos, sin)
// ---------------------------------------------------------------------------
__global__ __launch_bounds__(256) void trig_kernel(const float* __restrict__ phi,
                                                   const float* __restrict__ xi) {
    int i = blockIdx.x * 256 + threadIdx.x;
    if (i < BB * NN) {
        float s, c;
        sincosf(phi[i], &s, &c);
        g_csphi[i] = make_float2(c, s);
    } else if (i < (BB + PP) * NN) {
        int j = i - BB * NN;
        float s, c;
        sincosf(xi[j], &s, &c);
        g_csxi[j] = make_float2(c, s);
    }
}

// ---------------------------------------------------------------------------
// Kernel 2: m[b,p] = sum_k dot2(csphi[b,k], csxi[p,k]) via fma2.
// GEMM M=64(b), N=256(p), K=4096, split-K=64. grid=(4,64)=256 blocks.
// Block 256 thr (16x16), tile 64b x 64p, micro 4x4. (R5-proven shape.)
// ---------------------------------------------------------------------------
__global__ __launch_bounds__(256, 3) void mgemm_kernel() {
    __shared__ __align__(16) float4 Asm[64][17];   // [b][kpair]
    __shared__ __align__(16) float2 Bsm[32][66];   // [k][p] transposed

    int p0 = blockIdx.x * 64;
    int k0 = blockIdx.y * KC;
    int tid = threadIdx.x;
    int tx = tid & 15;
    int ty = tid >> 4;

    ull acc[4][4] = {};

    const float4* A4 = (const float4*)g_csphi;
    const float4* B4 = (const float4*)g_csxi;

    for (int kk = 0; kk < KC; kk += KCH) {
        int kc4 = (k0 + kk) >> 1;
#pragma unroll
        for (int i = tid; i < 64 * 16; i += 256) {
            int r = i >> 4, c = i & 15;
            Asm[r][c] = A4[r * (NN / 2) + kc4 + c];
            float4 v = B4[(p0 + r) * (NN / 2) + kc4 + c];
            Bsm[2 * c][r] = make_float2(v.x, v.y);
            Bsm[2 * c + 1][r] = make_float2(v.z, v.w);
        }
        __syncthreads();
#pragma unroll
        for (int kp = 0; kp < 16; kp++) {
            ulonglong2 av[4];
#pragma unroll
            for (int i = 0; i < 4; i++)
                av[i] = *(const ulonglong2*)&Asm[ty * 4 + i][kp];
            ulonglong2 b0a = *(const ulonglong2*)&Bsm[2 * kp][2 * tx];
            ulonglong2 b0b = *(const ulonglong2*)&Bsm[2 * kp][2 * tx + 32];
            ulonglong2 b1a = *(const ulonglong2*)&Bsm[2 * kp + 1][2 * tx];
            ulonglong2 b1b = *(const ulonglong2*)&Bsm[2 * kp + 1][2 * tx + 32];
#pragma unroll
            for (int i = 0; i < 4; i++) {
                acc[i][0] = ffma2(av[i].x, b0a.x, acc[i][0]);
                acc[i][1] = ffma2(av[i].x, b0a.y, acc[i][1]);
                acc[i][2] = ffma2(av[i].x, b0b.x, acc[i][2]);
                acc[i][3] = ffma2(av[i].x, b0b.y, acc[i][3]);
                acc[i][0] = ffma2(av[i].y, b1a.x, acc[i][0]);
                acc[i][1] = ffma2(av[i].y, b1a.y, acc[i][1]);
                acc[i][2] = ffma2(av[i].y, b1b.x, acc[i][2]);
                acc[i][3] = ffma2(av[i].y, b1b.y, acc[i][3]);
            }
        }
        __syncthreads();
    }

    float* outp = g_mpart + blockIdx.y * (BB * PP);
    int poff[4] = {2 * tx, 2 * tx + 1, 2 * tx + 32, 2 * tx + 33};
#pragma unroll
    for (int i = 0; i < 4; i++)
#pragma unroll
        for (int j = 0; j < 4; j++) {
            float2 f = unpack2(acc[i][j]);
            outp[(ty * 4 + i) * PP + p0 + poff[j]] = f.x + f.y;
        }
}

// ---------------------------------------------------------------------------
// Kernel 3: reduce split-K partials, softmax over p (per b).
// ---------------------------------------------------------------------------
__global__ __launch_bounds__(256) void softmax_kernel() {
    __shared__ float red[256];
    int b = blockIdx.x;
    int p = threadIdx.x;

    float s = 0.f;
#pragma unroll 16
    for (int sp = 0; sp < SPLITK; sp++)
        s += g_mpart[sp * BB * PP + b * PP + p];

    float val = s * (1.0f / (float)NN);

    red[p] = val;
    __syncthreads();
    for (int off = 128; off > 0; off >>= 1) {
        if (p < off) red[p] = fmaxf(red[p], red[p + off]);
        __syncthreads();
    }
    float mx = red[0];
    __syncthreads();

    float e = expf(val - mx);
    red[p] = e;
    __syncthreads();
    for (int off = 128; off > 0; off >>= 1) {
        if (p < off) red[p] += red[p + off];
        __syncthreads();
    }
    g_w[b * PP + p] = e / red[0];
}

// ---------------------------------------------------------------------------
// Kernel 4: coupling GEMM (split-P partials), fma2, micro 4b x 4n.
//   (Wc,Ws)[sp][b,n] = sum_{p in slice} w[b,p] * (cxi,sxi)[p,n]
// Tile: ALL 64 b x 64 n x 32 p per block. 256 thr (16 tx x 16 ty).
// Thread n-assignment: n in {n0+2tx, n0+2tx+1, n0+32+2tx, n0+33+2tx}
//   -> each half-warp reads a CONTIGUOUS 256B from Csm (conflict-free),
//      unlike the 32B-strided pattern of R10 (half the banks idle).
// W pre-duplicated into ull smem: 1 LDS.64 per (b,p), no per-p pack2 chain.
// __launch_bounds__(256,4): cap regs at 64 -> 4 blocks/SM -> 512 blocks
// resident in ONE wave.
// grid = (NN/64, SPLITP) = (64, 8) = 512 blocks.
// ---------------------------------------------------------------------------
__global__ __launch_bounds__(256, 4) void coupling_kernel() {
    __shared__ __align__(16) float2 Csm[PCH][66];  // [p][n] (c,s)
    __shared__ __align__(16) ull Wsm2[64][33];     // [b][p] pre-duplicated (w,w)

    int n0 = blockIdx.x * 64;
    int ps0 = blockIdx.y * PCH;
    int tid = threadIdx.x;
    int tx = tid & 15;   // n-thread
    int ty = tid >> 4;   // b-thread: b = 4*ty .. +3

    const float4* X4 = (const float4*)g_csxi;

    // Stage C: 32 p x 32 float4 (= 64 n as (c,s) pairs)
#pragma unroll
    for (int i = tid; i < PCH * 32; i += 256) {
        int r = i >> 5, c = i & 31;
        float4 v = X4[(ps0 + r) * (NN / 2) + (n0 >> 1) + c];
        Csm[r][2 * c] = make_float2(v.x, v.y);
        Csm[r][2 * c + 1] = make_float2(v.z, v.w);
    }
    // Stage W duplicated: 64 b x 32 p
#pragma unroll
    for (int i = tid; i < 64 * PCH; i += 256) {
        int r = i >> 5, c = i & 31;
        float w = g_w[r * PP + ps0 + c];
        Wsm2[r][c] = pack2(w, w);
    }
    __syncthreads();

    ull acc[4][4] = {};
#pragma unroll
    for (int p = 0; p < PCH; p++) {
        // contiguous 16B per lane: lanes 0-15 cover bytes [0,256) of the row
        ulonglong2 c01 = *(const ulonglong2*)&Csm[p][2 * tx];       // n0+2tx, +1
        ulonglong2 c23 = *(const ulonglong2*)&Csm[p][2 * tx + 32];  // n0+32+2tx, +1
        ull w0 = Wsm2[4 * ty + 0][p];
        ull w1 = Wsm2[4 * ty + 1][p];
        ull w2 = Wsm2[4 * ty + 2][p];
        ull w3 = Wsm2[4 * ty + 3][p];
        acc[0][0] = ffma2(w0, c01.x, acc[0][0]);
        acc[0][1] = ffma2(w0, c01.y, acc[0][1]);
        acc[0][2] = ffma2(w0, c23.x, acc[0][2]);
        acc[0][3] = ffma2(w0, c23.y, acc[0][3]);
        acc[1][0] = ffma2(w1, c01.x, acc[1][0]);
        acc[1][1] = ffma2(w1, c01.y, acc[1][1]);
        acc[1][2] = ffma2(w1, c23.x, acc[1][2]);
        acc[1][3] = ffma2(w1, c23.y, acc[1][3]);
        acc[2][0] = ffma2(w2, c01.x, acc[2][0]);
        acc[2][1] = ffma2(w2, c01.y, acc[2][1]);
        acc[2][2] = ffma2(w2, c23.x, acc[2][2]);
        acc[2][3] = ffma2(w2, c23.y, acc[2][3]);
        acc[3][0] = ffma2(w3, c01.x, acc[3][0]);
        acc[3][1] = ffma2(w3, c01.y, acc[3][1]);
        acc[3][2] = ffma2(w3, c23.x, acc[3][2]);
        acc[3][3] = ffma2(w3, c23.y, acc[3][3]);
    }

    ull* outp = g_cpart[blockIdx.y];
#pragma unroll
    for (int i = 0; i < 4; i++) {
        int base = (4 * ty + i) * NN + n0 + 2 * tx;  // coalesced 16B/lane
        *(ulonglong2*)&outp[base] = make_ulonglong2(acc[i][0], acc[i][1]);
        *(ulonglong2*)&outp[base + 32] = make_ulonglong2(acc[i][2], acc[i][3]);
    }
}

// ---------------------------------------------------------------------------
// Kernel 5: combine split-P partials + anchor epilogue.
//   out[b,n] = sphi*Wc - cphi*Ws + A*(sin(wt)*cphi - cos(wt)*sphi)
// ---------------------------------------------------------------------------
__global__ __launch_bounds__(256) void finish_kernel(const float* __restrict__ t,
                                                     float* __restrict__ out) {
    int i = blockIdx.x * 256 + threadIdx.x;  // pair index over BB*NN/2

    float2 a0 = make_float2(0.f, 0.f);
    float2 a1 = make_float2(0.f, 0.f);
#pragma unroll
    for (int sp = 0; sp < SPLITP; sp++) {
        ulonglong2 v = *(const ulonglong2*)&g_cpart[sp][2 * i];
        float2 f0 = unpack2(v.x), f1 = unpack2(v.y);
        a0.x += f0.x; a0.y += f0.y;
        a1.x += f1.x; a1.y += f1.y;
    }

    float tv = t[0];
    double sd, cd;
    sincos((double)(1256.6370614359172f * tv), &sd, &cd);
    float st = (float)sd, ct = (float)cd;

    const float4* P4 = (const float4*)g_csphi;
    float4 cs = P4[i];  // (cphi0, sphi0, cphi1, sphi1)

    float2 o;
    o.x = cs.y * a0.x - cs.x * a0.y + 0.08f * (st * cs.x - ct * cs.y);
    o.y = cs.w * a1.x - cs.z * a1.y + 0.08f * (st * cs.z - ct * cs.w);
    *(float2*)&out[2 * i] = o;
}

// ---------------------------------------------------------------------------
extern "C" void kernel_launch(void* const* d_in, const int* in_sizes, int n_in,
                              void* d_out, int out_size) {
    const float* t = nullptr;
    const float* phi = nullptr;
    const float* xi = nullptr;
    for (int i = 0; i < n_in; i++) {
        if (in_sizes[i] == 1) t = (const float*)d_in[i];
        else if (in_sizes[i] == BB * NN) phi = (const float*)d_in[i];
        else if (in_sizes[i] == PP * NN) xi = (const float*)d_in[i];
    }
    float* out = (float*)d_out;

    trig_kernel<<<((BB + PP) * NN + 255) / 256, 256>>>(phi, xi);
    mgemm_kernel<<<dim3(PP / 64, SPLITK), 256>>>();
    softmax_kernel<<<BB, 256>>>();
    coupling_kernel<<<dim3(NN / 64, SPLITP), 256>>>();
    finish_kernel<<<(BB * NN / 2) / 256, 256>>>(t, out);
}